// round 2
// baseline (speedup 1.0000x reference)
#include <cuda_runtime.h>
#include <math.h>

#define BATCH_MAX 2048
typedef unsigned long long ull;

// ---------------- scratch (device globals; no allocation) ----------------
__device__ float4 g_fcwT[8192];          // fc_w transposed: [idx][k]
__device__ float4 g_A[16 * 1024];        // folded fc2+dconv1 weights: [oc*1024+px][k]
__device__ float  g_Beff[16 * 1024];     // folded bias
__device__ float  g_ang[BATCH_MAX * 4];  // angles out of frontend
__device__ float  g_q[BATCH_MAX * 4];    // quantum expvals

// ---------------- packed f32x2 helpers ----------------
__device__ __forceinline__ ull pk2(float lo, float hi) {
    ull r;
    asm("mov.b64 %0, {%1, %2};" : "=l"(r) : "f"(lo), "f"(hi));
    return r;
}
__device__ __forceinline__ float2 upk2(ull v) {
    float2 f;
    asm("mov.b64 {%0, %1}, %2;" : "=f"(f.x), "=f"(f.y) : "l"(v));
    return f;
}
__device__ __forceinline__ ull ffma2(ull a, ull b, ull c) {
    ull d;
    asm("fma.rn.f32x2 %0, %1, %2, %3;" : "=l"(d) : "l"(a), "l"(b), "l"(c));
    return d;
}
__device__ __forceinline__ ull dupbits(float w) {
    unsigned u = __float_as_uint(w);
    return ((ull)u << 32) | (ull)u;
}

// ---------------- prep: fc_w transpose + fc2/dconv1 fold ----------------
__global__ void prep_kernel(const float* __restrict__ fc_w,      // (4,8192)
                            const float* __restrict__ fc2_w,     // (8192,4)
                            const float* __restrict__ fc2_b,     // (8192)
                            const float* __restrict__ dconv1_w,  // (16,8,3,3)
                            const float* __restrict__ dconv1_b)  // (16)
{
    int i = blockIdx.x * blockDim.x + threadIdx.x;
    if (i < 8192) {
        g_fcwT[i] = make_float4(fc_w[i], fc_w[8192 + i], fc_w[16384 + i], fc_w[24576 + i]);
    }
    if (i < 16 * 1024) {
        int oc = i >> 10, px = i & 1023, y = px >> 5, x = px & 31;
        float s0 = 0.f, s1 = 0.f, s2 = 0.f, s3 = 0.f;
        float bs = dconv1_b[oc];
        for (int c = 0; c < 8; c++) {
            for (int dy = 0; dy < 3; dy++) {
                int iy = y + dy - 1;
                if ((unsigned)iy >= 32u) continue;
                for (int dx = 0; dx < 3; dx++) {
                    int ix = x + dx - 1;
                    if ((unsigned)ix >= 32u) continue;
                    int idx = (c << 10) + (iy << 5) + ix;
                    float w = dconv1_w[((oc * 8 + c) * 3 + dy) * 3 + dx];
                    float4 f = reinterpret_cast<const float4*>(fc2_w)[idx];
                    s0 = fmaf(w, f.x, s0);
                    s1 = fmaf(w, f.y, s1);
                    s2 = fmaf(w, f.z, s2);
                    s3 = fmaf(w, f.w, s3);
                    bs = fmaf(w, fc2_b[idx], bs);
                }
            }
        }
        g_A[i] = make_float4(s0, s1, s2, s3);
        g_Beff[i] = bs;
    }
}

// ============================================================================
// FRONTEND: conv1+relu -> conv2+relu -> fc (angles).  thread = (row y, 4 px)
// ============================================================================
struct FrontS {
    float sx[3][34][40];     // padded input, data at [1+y][4+x]
    float sh1[8][34][40];    // padded conv1 group output
    ull   dsw1[432];         // conv1 w dup: [(ic*3+dy)*16+oc][dx]
    ull   dsw2[1152];        // conv2 w dup: [(ic*3+dy)*8+o][dx]
    float sb1[16];
    float sb2[8];
    float red[8][4];
};

__global__ __launch_bounds__(256, 2) void frontend_kernel(
    const float* __restrict__ x,
    const float* __restrict__ w1, const float* __restrict__ b1,
    const float* __restrict__ w2, const float* __restrict__ b2,
    const float* __restrict__ fcb)
{
    extern __shared__ char raw[];
    FrontS& S = *reinterpret_cast<FrontS*>(raw);
    const int bidx = blockIdx.x, t = threadIdx.x;
    const int y = t >> 3, x0 = (t & 7) << 2;

    // zero padded buffers (float4)
    {
        float4 z = make_float4(0.f, 0.f, 0.f, 0.f);
        float4* px4 = reinterpret_cast<float4*>(&S.sx[0][0][0]);
        for (int i = t; i < 3 * 34 * 10; i += 256) px4[i] = z;
        float4* ph4 = reinterpret_cast<float4*>(&S.sh1[0][0][0]);
        for (int i = t; i < 8 * 34 * 10; i += 256) ph4[i] = z;
    }
    // weights (duplicated into both f32x2 lanes)
    for (int i = t; i < 432; i += 256) {
        int dx = i % 3, j = i / 3;
        int oc = j % 16, k = j / 16;
        int dy = k % 3, ic = k / 3;
        S.dsw1[i] = dupbits(w1[((oc * 3 + ic) * 3 + dy) * 3 + dx]);
    }
    for (int i = t; i < 1152; i += 256) {
        int dx = i % 3, j = i / 3;
        int o = j % 8, k = j / 8;
        int dy = k % 3, ic = k / 3;
        S.dsw2[i] = dupbits(w2[((o * 16 + ic) * 3 + dy) * 3 + dx]);
    }
    if (t < 16) S.sb1[t] = b1[t];
    if (t < 8)  S.sb2[t] = b2[t];
    __syncthreads();

    const float* xb = x + bidx * 3072;
    for (int i = t; i < 3072; i += 256) {
        int c = i >> 10, p = i & 1023;
        S.sx[c][1 + (p >> 5)][4 + (p & 31)] = xb[i];
    }
    __syncthreads();

    // conv2 accumulators (persist across conv1 groups)
    ull a2_01[8], a2_23[8];
    #pragma unroll
    for (int o = 0; o < 8; o++) { ull b = dupbits(S.sb2[o]); a2_01[o] = b; a2_23[o] = b; }

    for (int g = 0; g < 2; g++) {
        // ---- conv1, oc group g ----
        ull a1_01[8], a1_23[8];
        #pragma unroll
        for (int o = 0; o < 8; o++) { ull b = dupbits(S.sb1[g * 8 + o]); a1_01[o] = b; a1_23[o] = b; }

        #pragma unroll
        for (int ic = 0; ic < 3; ic++)
            #pragma unroll
            for (int dy = 0; dy < 3; dy++) {
                const float* base = &S.sx[ic][y + dy][0];
                float v0 = base[x0 + 3];
                float4 vm = *reinterpret_cast<const float4*>(base + x0 + 4);
                float v5 = base[x0 + 8];
                ull q0 = pk2(v0, vm.x), q1 = pk2(vm.x, vm.y), q2 = pk2(vm.y, vm.z);
                ull q3 = pk2(vm.z, vm.w), q4 = pk2(vm.w, v5);
                #pragma unroll
                for (int o = 0; o < 8; o++) {
                    int wi = ((ic * 3 + dy) * 16 + g * 8 + o) * 3;
                    ull w0 = S.dsw1[wi], wA = S.dsw1[wi + 1], wB = S.dsw1[wi + 2];
                    a1_01[o] = ffma2(q0, w0, a1_01[o]);
                    a1_01[o] = ffma2(q1, wA, a1_01[o]);
                    a1_01[o] = ffma2(q2, wB, a1_01[o]);
                    a1_23[o] = ffma2(q2, w0, a1_23[o]);
                    a1_23[o] = ffma2(q3, wA, a1_23[o]);
                    a1_23[o] = ffma2(q4, wB, a1_23[o]);
                }
            }
        #pragma unroll
        for (int o = 0; o < 8; o++) {
            float2 l = upk2(a1_01[o]), h = upk2(a1_23[o]);
            float4 r = make_float4(fmaxf(l.x, 0.f), fmaxf(l.y, 0.f),
                                   fmaxf(h.x, 0.f), fmaxf(h.y, 0.f));
            *reinterpret_cast<float4*>(&S.sh1[o][1 + y][4 + x0]) = r;
        }
        __syncthreads();

        // ---- conv2 partial over these 8 input channels ----
        #pragma unroll
        for (int icg = 0; icg < 8; icg++) {
            int ic16 = g * 8 + icg;
            #pragma unroll
            for (int dy = 0; dy < 3; dy++) {
                const float* base = &S.sh1[icg][y + dy][0];
                float v0 = base[x0 + 3];
                float4 vm = *reinterpret_cast<const float4*>(base + x0 + 4);
                float v5 = base[x0 + 8];
                ull q0 = pk2(v0, vm.x), q1 = pk2(vm.x, vm.y), q2 = pk2(vm.y, vm.z);
                ull q3 = pk2(vm.z, vm.w), q4 = pk2(vm.w, v5);
                #pragma unroll
                for (int o = 0; o < 8; o++) {
                    int wi = ((ic16 * 3 + dy) * 8 + o) * 3;
                    ull w0 = S.dsw2[wi], wA = S.dsw2[wi + 1], wB = S.dsw2[wi + 2];
                    a2_01[o] = ffma2(q0, w0, a2_01[o]);
                    a2_01[o] = ffma2(q1, wA, a2_01[o]);
                    a2_01[o] = ffma2(q2, wB, a2_01[o]);
                    a2_23[o] = ffma2(q2, w0, a2_23[o]);
                    a2_23[o] = ffma2(q3, wA, a2_23[o]);
                    a2_23[o] = ffma2(q4, wB, a2_23[o]);
                }
            }
        }
        __syncthreads();  // before next group overwrites sh1
    }

    // ---- relu + fc into 4 angle partials ----
    float angk[4] = {0.f, 0.f, 0.f, 0.f};
    #pragma unroll
    for (int o = 0; o < 8; o++) {
        float2 l = upk2(a2_01[o]), h = upk2(a2_23[o]);
        float hv[4] = {fmaxf(l.x, 0.f), fmaxf(l.y, 0.f), fmaxf(h.x, 0.f), fmaxf(h.y, 0.f)};
        #pragma unroll
        for (int p = 0; p < 4; p++) {
            float4 f = g_fcwT[(o << 10) + (y << 5) + x0 + p];
            angk[0] = fmaf(hv[p], f.x, angk[0]);
            angk[1] = fmaf(hv[p], f.y, angk[1]);
            angk[2] = fmaf(hv[p], f.z, angk[2]);
            angk[3] = fmaf(hv[p], f.w, angk[3]);
        }
    }
    #pragma unroll
    for (int k = 0; k < 4; k++)
        #pragma unroll
        for (int off = 16; off > 0; off >>= 1)
            angk[k] += __shfl_xor_sync(0xffffffffu, angk[k], off);
    const int wrp = t >> 5, ln = t & 31;
    if (ln == 0) {
        #pragma unroll
        for (int k = 0; k < 4; k++) S.red[wrp][k] = angk[k];
    }
    __syncthreads();
    if (t < 4) {
        float s = 0.f;
        #pragma unroll
        for (int w = 0; w < 8; w++) s += S.red[w][t];
        g_ang[bidx * 4 + t] = s + fcb[t];
    }
}

// ---------------- quantum: 1 thread = 1 batch element ----------------
__global__ void quantum_kernel(const float* __restrict__ qw, int batch)
{
    int b = blockIdx.x * blockDim.x + threadIdx.x;
    if (b >= batch) return;

    float sr[16], si[16];
    #pragma unroll
    for (int i = 0; i < 16; i++) { sr[i] = 0.f; si[i] = 0.f; }
    sr[0] = 1.f;

    #pragma unroll
    for (int w = 0; w < 4; w++) {
        float h = 0.5f * g_ang[b * 4 + w];
        float c = cosf(h), s = sinf(h);
        const int bit = 1 << (3 - w);
        #pragma unroll
        for (int i = 0; i < 16; i++) {
            if (i & bit) continue;
            int j = i | bit;
            float ar = sr[i], ai = si[i], br = sr[j], bi = si[j];
            sr[i] = fmaf(c, ar,  s * bi);  si[i] = fmaf(c, ai, -s * br);
            sr[j] = fmaf(c, br,  s * ai);  si[j] = fmaf(c, bi, -s * ar);
        }
    }

    #pragma unroll
    for (int l = 0; l < 3; l++) {
        #pragma unroll
        for (int w = 0; w < 4; w++) {
            float phi = qw[(l * 4 + w) * 3 + 0];
            float th  = qw[(l * 4 + w) * 3 + 1];
            float om  = qw[(l * 4 + w) * 3 + 2];
            float ct = cosf(0.5f * th), st = sinf(0.5f * th);
            float a = 0.5f * (phi + om), d = 0.5f * (phi - om);
            float ca = cosf(a), sa = sinf(a), cd = cosf(d), sd = sinf(d);
            float u00r =  ca * ct, u00i = -sa * ct;
            float u01r = -cd * st, u01i = -sd * st;
            float u10r =  cd * st, u10i = -sd * st;
            float u11r =  ca * ct, u11i =  sa * ct;
            const int bit = 1 << (3 - w);
            #pragma unroll
            for (int i = 0; i < 16; i++) {
                if (i & bit) continue;
                int j = i | bit;
                float ar = sr[i], ai = si[i], br = sr[j], bi = si[j];
                sr[i] = u00r * ar - u00i * ai + u01r * br - u01i * bi;
                si[i] = u00r * ai + u00i * ar + u01r * bi + u01i * br;
                sr[j] = u10r * ar - u10i * ai + u11r * br - u11i * bi;
                si[j] = u10r * ai + u10i * ar + u11r * bi + u11i * br;
            }
        }
        const int r = (l % 3) + 1;
        #pragma unroll
        for (int w = 0; w < 4; w++) {
            int tq = (w + r) & 3;
            const int cb = 1 << (3 - w), tb = 1 << (3 - tq);
            #pragma unroll
            for (int i = 0; i < 16; i++) {
                if ((i & cb) && !(i & tb)) {
                    int j = i | tb;
                    float tr = sr[i]; sr[i] = sr[j]; sr[j] = tr;
                    float ti = si[i]; si[i] = si[j]; si[j] = ti;
                }
            }
        }
    }

    #pragma unroll
    for (int w = 0; w < 4; w++) {
        const int bit = 1 << (3 - w);
        float e = 0.f;
        #pragma unroll
        for (int i = 0; i < 16; i++) {
            float p = sr[i] * sr[i] + si[i] * si[i];
            e += (i & bit) ? -p : p;
        }
        g_q[b * 4 + w] = e;
    }
}

// ============================================================================
// BACKEND: folded dconv1 + relu -> dconv2 + sigmoid.  2 images per block.
// ============================================================================
struct BackS {
    float sact[2][8][34][40];  // per-image padded dconv1 group output (87KB)
    ull   dsw[432];            // dconv2 w dup: [(ic*3+dy)*3+o][dx]
    float sb[3];
};

__global__ __launch_bounds__(256, 2) void backend_kernel(
    const float* __restrict__ w2, const float* __restrict__ b2,
    float* __restrict__ out)
{
    extern __shared__ char raw[];
    BackS& S = *reinterpret_cast<BackS*>(raw);
    const int bid = blockIdx.x, t = threadIdx.x;
    const int b0 = 2 * bid, b1 = b0 + 1;
    const int y = t >> 3, x0 = (t & 7) << 2;

    {
        float4 z = make_float4(0.f, 0.f, 0.f, 0.f);
        float4* p4 = reinterpret_cast<float4*>(&S.sact[0][0][0][0]);
        for (int i = t; i < 2 * 8 * 34 * 10; i += 256) p4[i] = z;
    }
    for (int i = t; i < 432; i += 256) {
        int dx = i % 3, j = i / 3;
        int o = j % 3, k = j / 3;
        int dy = k % 3, ic = k / 3;
        S.dsw[i] = dupbits(w2[((o * 16 + ic) * 3 + dy) * 3 + dx]);
    }
    if (t < 3) S.sb[t] = b2[t];

    float qa[4], qb[4];
    #pragma unroll
    for (int k = 0; k < 4; k++) { qa[k] = g_q[b0 * 4 + k]; qb[k] = g_q[b1 * 4 + k]; }
    __syncthreads();

    ull acc01[2][3], acc23[2][3];
    #pragma unroll
    for (int o = 0; o < 3; o++) {
        ull b = dupbits(S.sb[o]);
        acc01[0][o] = b; acc23[0][o] = b;
        acc01[1][o] = b; acc23[1][o] = b;
    }

    for (int g = 0; g < 2; g++) {
        // ---- stage 1: folded dconv1 (4 FMA/elem), oc group g, both images ----
        #pragma unroll
        for (int o8 = 0; o8 < 8; o8++) {
            int oc = g * 8 + o8;
            int idx = (oc << 10) + (y << 5) + x0;
            float4 a0 = g_A[idx], a1 = g_A[idx + 1], a2 = g_A[idx + 2], a3 = g_A[idx + 3];
            float4 be = *reinterpret_cast<const float4*>(&g_Beff[idx]);
            float4 r0, r1;
            {
                float v0 = fmaf(qa[0], a0.x, fmaf(qa[1], a0.y, fmaf(qa[2], a0.z, fmaf(qa[3], a0.w, be.x))));
                float v1 = fmaf(qa[0], a1.x, fmaf(qa[1], a1.y, fmaf(qa[2], a1.z, fmaf(qa[3], a1.w, be.y))));
                float v2 = fmaf(qa[0], a2.x, fmaf(qa[1], a2.y, fmaf(qa[2], a2.z, fmaf(qa[3], a2.w, be.z))));
                float v3 = fmaf(qa[0], a3.x, fmaf(qa[1], a3.y, fmaf(qa[2], a3.z, fmaf(qa[3], a3.w, be.w))));
                r0 = make_float4(fmaxf(v0, 0.f), fmaxf(v1, 0.f), fmaxf(v2, 0.f), fmaxf(v3, 0.f));
            }
            {
                float v0 = fmaf(qb[0], a0.x, fmaf(qb[1], a0.y, fmaf(qb[2], a0.z, fmaf(qb[3], a0.w, be.x))));
                float v1 = fmaf(qb[0], a1.x, fmaf(qb[1], a1.y, fmaf(qb[2], a1.z, fmaf(qb[3], a1.w, be.y))));
                float v2 = fmaf(qb[0], a2.x, fmaf(qb[1], a2.y, fmaf(qb[2], a2.z, fmaf(qb[3], a2.w, be.z))));
                float v3 = fmaf(qb[0], a3.x, fmaf(qb[1], a3.y, fmaf(qb[2], a3.z, fmaf(qb[3], a3.w, be.w))));
                r1 = make_float4(fmaxf(v0, 0.f), fmaxf(v1, 0.f), fmaxf(v2, 0.f), fmaxf(v3, 0.f));
            }
            *reinterpret_cast<float4*>(&S.sact[0][o8][1 + y][4 + x0]) = r0;
            *reinterpret_cast<float4*>(&S.sact[1][o8][1 + y][4 + x0]) = r1;
        }
        __syncthreads();

        // ---- stage 2: dconv2 partial over these 8 input channels ----
        #pragma unroll
        for (int img = 0; img < 2; img++) {
            #pragma unroll
            for (int icg = 0; icg < 8; icg++) {
                int ic16 = g * 8 + icg;
                #pragma unroll
                for (int dy = 0; dy < 3; dy++) {
                    const float* base = &S.sact[img][icg][y + dy][0];
                    float v0 = base[x0 + 3];
                    float4 vm = *reinterpret_cast<const float4*>(base + x0 + 4);
                    float v5 = base[x0 + 8];
                    ull q0 = pk2(v0, vm.x), q1 = pk2(vm.x, vm.y), q2 = pk2(vm.y, vm.z);
                    ull q3 = pk2(vm.z, vm.w), q4 = pk2(vm.w, v5);
                    #pragma unroll
                    for (int o = 0; o < 3; o++) {
                        int wi = ((ic16 * 3 + dy) * 3 + o) * 3;
                        ull w0 = S.dsw[wi], wA = S.dsw[wi + 1], wB = S.dsw[wi + 2];
                        acc01[img][o] = ffma2(q0, w0, acc01[img][o]);
                        acc01[img][o] = ffma2(q1, wA, acc01[img][o]);
                        acc01[img][o] = ffma2(q2, wB, acc01[img][o]);
                        acc23[img][o] = ffma2(q2, w0, acc23[img][o]);
                        acc23[img][o] = ffma2(q3, wA, acc23[img][o]);
                        acc23[img][o] = ffma2(q4, wB, acc23[img][o]);
                    }
                }
            }
        }
        __syncthreads();  // before next group overwrites sact
    }

    // ---- sigmoid epilogue ----
    #pragma unroll
    for (int img = 0; img < 2; img++) {
        float* ob = out + (b0 + img) * 3072;
        #pragma unroll
        for (int o = 0; o < 3; o++) {
            float2 l = upk2(acc01[img][o]), h = upk2(acc23[img][o]);
            float4 r = make_float4(1.f / (1.f + __expf(-l.x)),
                                   1.f / (1.f + __expf(-l.y)),
                                   1.f / (1.f + __expf(-h.x)),
                                   1.f / (1.f + __expf(-h.y)));
            *reinterpret_cast<float4*>(&ob[(o << 10) + (y << 5) + x0]) = r;
        }
    }
}

// ---------------- launch ----------------
extern "C" void kernel_launch(void* const* d_in, const int* in_sizes, int n_in,
                              void* d_out, int out_size)
{
    const float* x        = (const float*)d_in[0];
    const float* conv1_w  = (const float*)d_in[1];
    const float* conv1_b  = (const float*)d_in[2];
    const float* conv2_w  = (const float*)d_in[3];
    const float* conv2_b  = (const float*)d_in[4];
    const float* fc_w     = (const float*)d_in[5];
    const float* fc_b     = (const float*)d_in[6];
    const float* q_w      = (const float*)d_in[7];
    const float* fc2_w    = (const float*)d_in[8];
    const float* fc2_b    = (const float*)d_in[9];
    const float* dconv1_w = (const float*)d_in[10];
    const float* dconv1_b = (const float*)d_in[11];
    const float* dconv2_w = (const float*)d_in[12];
    const float* dconv2_b = (const float*)d_in[13];
    float* out = (float*)d_out;

    const int batch = in_sizes[0] / (3 * 32 * 32);

    cudaFuncSetAttribute(frontend_kernel, cudaFuncAttributeMaxDynamicSharedMemorySize,
                         (int)sizeof(FrontS));
    cudaFuncSetAttribute(backend_kernel, cudaFuncAttributeMaxDynamicSharedMemorySize,
                         (int)sizeof(BackS));

    prep_kernel<<<64, 256>>>(fc_w, fc2_w, fc2_b, dconv1_w, dconv1_b);
    frontend_kernel<<<batch, 256, sizeof(FrontS)>>>(x, conv1_w, conv1_b,
                                                    conv2_w, conv2_b, fc_b);
    quantum_kernel<<<(batch + 255) / 256, 256>>>(q_w, batch);
    backend_kernel<<<batch / 2, 256, sizeof(BackS)>>>(dconv2_w, dconv2_b, out);
}

// round 3
// speedup vs baseline: 1.5103x; 1.5103x over previous
#include <cuda_runtime.h>
#include <math.h>

#define BATCH_MAX 2048
typedef unsigned long long ull;

// ---------------- scratch (device globals; no allocation) ----------------
__device__ float4 g_fcwT[8192];          // fc_w transposed: [idx][k]
__device__ float4 g_A[16 * 1024];        // folded fc2+dconv1 weights: [oc*1024+px][k]
__device__ float  g_Beff[16 * 1024];     // folded bias
__device__ float  g_ang[BATCH_MAX * 4];  // angles out of frontend
__device__ float  g_q[BATCH_MAX * 4];    // quantum expvals

// ---------------- packed f32x2 helpers ----------------
__device__ __forceinline__ ull pk2(float lo, float hi) {
    ull r;
    asm("mov.b64 %0, {%1, %2};" : "=l"(r) : "f"(lo), "f"(hi));
    return r;
}
__device__ __forceinline__ float2 upk2(ull v) {
    float2 f;
    asm("mov.b64 {%0, %1}, %2;" : "=f"(f.x), "=f"(f.y) : "l"(v));
    return f;
}
__device__ __forceinline__ ull ffma2(ull a, ull b, ull c) {
    ull d;
    asm("fma.rn.f32x2 %0, %1, %2, %3;" : "=l"(d) : "l"(a), "l"(b), "l"(c));
    return d;
}
__device__ __forceinline__ ull dupbits(float w) {
    unsigned u = __float_as_uint(w);
    return ((ull)u << 32) | (ull)u;
}

// ---------------- prep: fc_w transpose + fc2/dconv1 fold ----------------
__global__ void prep_kernel(const float* __restrict__ fc_w,      // (4,8192)
                            const float* __restrict__ fc2_w,     // (8192,4)
                            const float* __restrict__ fc2_b,     // (8192)
                            const float* __restrict__ dconv1_w,  // (16,8,3,3)
                            const float* __restrict__ dconv1_b)  // (16)
{
    int i = blockIdx.x * blockDim.x + threadIdx.x;
    if (i < 8192) {
        g_fcwT[i] = make_float4(fc_w[i], fc_w[8192 + i], fc_w[16384 + i], fc_w[24576 + i]);
    }
    if (i < 16 * 1024) {
        int oc = i >> 10, px = i & 1023, y = px >> 5, x = px & 31;
        float s0 = 0.f, s1 = 0.f, s2 = 0.f, s3 = 0.f;
        float bs = dconv1_b[oc];
        for (int c = 0; c < 8; c++) {
            for (int dy = 0; dy < 3; dy++) {
                int iy = y + dy - 1;
                if ((unsigned)iy >= 32u) continue;
                for (int dx = 0; dx < 3; dx++) {
                    int ix = x + dx - 1;
                    if ((unsigned)ix >= 32u) continue;
                    int idx = (c << 10) + (iy << 5) + ix;
                    float w = dconv1_w[((oc * 8 + c) * 3 + dy) * 3 + dx];
                    float4 f = reinterpret_cast<const float4*>(fc2_w)[idx];
                    s0 = fmaf(w, f.x, s0);
                    s1 = fmaf(w, f.y, s1);
                    s2 = fmaf(w, f.z, s2);
                    s3 = fmaf(w, f.w, s3);
                    bs = fmaf(w, fc2_b[idx], bs);
                }
            }
        }
        g_A[i] = make_float4(s0, s1, s2, s3);
        g_Beff[i] = bs;
    }
}

// ============================================================================
// FRONTEND: conv1(scalar)+relu -> conv2(f32x2)+relu -> fc.
// thread = (row y = t>>3, 4 contiguous px at x0 = (t&7)*4)
// ============================================================================
struct FrontS {
    float sx[3][34][40];     // padded input, data at [1+y][4+x]
    float sh1[8][34][40];    // padded conv1 group output (8 ch at a time)
    float sw1[432];          // conv1 w: [(ic*3+dy)*16+oc][dx] scalar
    ull   dsw2[1152];        // conv2 w dup: [(ic*3+dy)*8+o][dx]
    float sb1[16];
    float sb2[8];
    float red[8][4];
};

__global__ __launch_bounds__(256, 2) void frontend_kernel(
    const float* __restrict__ x,
    const float* __restrict__ w1, const float* __restrict__ b1,
    const float* __restrict__ w2, const float* __restrict__ b2,
    const float* __restrict__ fcb)
{
    extern __shared__ char raw[];
    FrontS& S = *reinterpret_cast<FrontS*>(raw);
    const int bidx = blockIdx.x, t = threadIdx.x;
    const int y = t >> 3, x0 = (t & 7) << 2;

    {
        float4 z = make_float4(0.f, 0.f, 0.f, 0.f);
        float4* px4 = reinterpret_cast<float4*>(&S.sx[0][0][0]);
        for (int i = t; i < 3 * 34 * 10; i += 256) px4[i] = z;
        float4* ph4 = reinterpret_cast<float4*>(&S.sh1[0][0][0]);
        for (int i = t; i < 8 * 34 * 10; i += 256) ph4[i] = z;
    }
    for (int i = t; i < 432; i += 256) {
        int dx = i % 3, j = i / 3;
        int oc = j % 16, k = j / 16;
        int dy = k % 3, ic = k / 3;
        S.sw1[i] = w1[((oc * 3 + ic) * 3 + dy) * 3 + dx];
    }
    for (int i = t; i < 1152; i += 256) {
        int dx = i % 3, j = i / 3;
        int o = j % 8, k = j / 8;
        int dy = k % 3, ic = k / 3;
        S.dsw2[i] = dupbits(w2[((o * 16 + ic) * 3 + dy) * 3 + dx]);
    }
    if (t < 16) S.sb1[t] = b1[t];
    if (t < 8)  S.sb2[t] = b2[t];
    __syncthreads();

    const float* xb = x + bidx * 3072;
    for (int i = t; i < 3072; i += 256) {
        int c = i >> 10, p = i & 1023;
        S.sx[c][1 + (p >> 5)][4 + (p & 31)] = xb[i];
    }
    __syncthreads();

    // conv2 accumulators: 8 oc x 2 pixel-pairs (f32x2)
    ull a2_01[8], a2_23[8];
    #pragma unroll
    for (int o = 0; o < 8; o++) { ull b = dupbits(S.sb2[o]); a2_01[o] = b; a2_23[o] = b; }

    for (int g = 0; g < 2; g++) {
        // ---- conv1 group g (scalar, 8 oc, 4 px) ----
        float a1[8][4];
        #pragma unroll
        for (int o = 0; o < 8; o++) {
            float b = S.sb1[g * 8 + o];
            #pragma unroll
            for (int p = 0; p < 4; p++) a1[o][p] = b;
        }
        #pragma unroll
        for (int ic = 0; ic < 3; ic++)
            #pragma unroll
            for (int dy = 0; dy < 3; dy++) {
                const float* base = &S.sx[ic][y + dy][0];
                float v0 = base[x0 + 3];
                float4 vm = *reinterpret_cast<const float4*>(base + x0 + 4);
                float v5 = base[x0 + 8];
                float v[6] = {v0, vm.x, vm.y, vm.z, vm.w, v5};
                #pragma unroll
                for (int o = 0; o < 8; o++) {
                    int wi = ((ic * 3 + dy) * 16 + g * 8 + o) * 3;
                    float w0 = S.sw1[wi], wA = S.sw1[wi + 1], wB = S.sw1[wi + 2];
                    #pragma unroll
                    for (int p = 0; p < 4; p++)
                        a1[o][p] = fmaf(v[p], w0, fmaf(v[p + 1], wA, fmaf(v[p + 2], wB, a1[o][p])));
                }
            }
        #pragma unroll
        for (int o = 0; o < 8; o++) {
            float4 r = make_float4(fmaxf(a1[o][0], 0.f), fmaxf(a1[o][1], 0.f),
                                   fmaxf(a1[o][2], 0.f), fmaxf(a1[o][3], 0.f));
            *reinterpret_cast<float4*>(&S.sh1[o][1 + y][4 + x0]) = r;
        }
        __syncthreads();

        // ---- conv2 partial over these 8 input channels (f32x2) ----
        #pragma unroll
        for (int icg = 0; icg < 8; icg++) {
            int ic16 = g * 8 + icg;
            #pragma unroll
            for (int dy = 0; dy < 3; dy++) {
                const float* base = &S.sh1[icg][y + dy][0];
                float v0 = base[x0 + 3];
                float4 vm = *reinterpret_cast<const float4*>(base + x0 + 4);
                float v5 = base[x0 + 8];
                ull q0 = pk2(v0, vm.x), q1 = pk2(vm.x, vm.y), q2 = pk2(vm.y, vm.z);
                ull q3 = pk2(vm.z, vm.w), q4 = pk2(vm.w, v5);
                #pragma unroll
                for (int o = 0; o < 8; o++) {
                    int wi = ((ic16 * 3 + dy) * 8 + o) * 3;
                    ull w0 = S.dsw2[wi], wA = S.dsw2[wi + 1], wB = S.dsw2[wi + 2];
                    a2_01[o] = ffma2(q0, w0, a2_01[o]);
                    a2_01[o] = ffma2(q1, wA, a2_01[o]);
                    a2_01[o] = ffma2(q2, wB, a2_01[o]);
                    a2_23[o] = ffma2(q2, w0, a2_23[o]);
                    a2_23[o] = ffma2(q3, wA, a2_23[o]);
                    a2_23[o] = ffma2(q4, wB, a2_23[o]);
                }
            }
        }
        __syncthreads();  // before next group overwrites sh1
    }

    // ---- relu + fc into 4 angle partials ----
    float angk[4] = {0.f, 0.f, 0.f, 0.f};
    #pragma unroll
    for (int o = 0; o < 8; o++) {
        float2 l = upk2(a2_01[o]), h = upk2(a2_23[o]);
        float hv[4] = {fmaxf(l.x, 0.f), fmaxf(l.y, 0.f), fmaxf(h.x, 0.f), fmaxf(h.y, 0.f)};
        #pragma unroll
        for (int p = 0; p < 4; p++) {
            float4 f = g_fcwT[(o << 10) + (y << 5) + x0 + p];
            angk[0] = fmaf(hv[p], f.x, angk[0]);
            angk[1] = fmaf(hv[p], f.y, angk[1]);
            angk[2] = fmaf(hv[p], f.z, angk[2]);
            angk[3] = fmaf(hv[p], f.w, angk[3]);
        }
    }
    #pragma unroll
    for (int k = 0; k < 4; k++)
        #pragma unroll
        for (int off = 16; off > 0; off >>= 1)
            angk[k] += __shfl_xor_sync(0xffffffffu, angk[k], off);
    const int wrp = t >> 5, ln = t & 31;
    if (ln == 0) {
        #pragma unroll
        for (int k = 0; k < 4; k++) S.red[wrp][k] = angk[k];
    }
    __syncthreads();
    if (t < 4) {
        float s = 0.f;
        #pragma unroll
        for (int w = 0; w < 8; w++) s += S.red[w][t];
        g_ang[bidx * 4 + t] = s + fcb[t];
    }
}

// ---------------- quantum: 1 thread = 1 batch element ----------------
__global__ void quantum_kernel(const float* __restrict__ qw, int batch)
{
    int b = blockIdx.x * blockDim.x + threadIdx.x;
    if (b >= batch) return;

    float sr[16], si[16];
    #pragma unroll
    for (int i = 0; i < 16; i++) { sr[i] = 0.f; si[i] = 0.f; }
    sr[0] = 1.f;

    #pragma unroll
    for (int w = 0; w < 4; w++) {
        float h = 0.5f * g_ang[b * 4 + w];
        float c = cosf(h), s = sinf(h);
        const int bit = 1 << (3 - w);
        #pragma unroll
        for (int i = 0; i < 16; i++) {
            if (i & bit) continue;
            int j = i | bit;
            float ar = sr[i], ai = si[i], br = sr[j], bi = si[j];
            sr[i] = fmaf(c, ar,  s * bi);  si[i] = fmaf(c, ai, -s * br);
            sr[j] = fmaf(c, br,  s * ai);  si[j] = fmaf(c, bi, -s * ar);
        }
    }

    #pragma unroll
    for (int l = 0; l < 3; l++) {
        #pragma unroll
        for (int w = 0; w < 4; w++) {
            float phi = qw[(l * 4 + w) * 3 + 0];
            float th  = qw[(l * 4 + w) * 3 + 1];
            float om  = qw[(l * 4 + w) * 3 + 2];
            float ct = cosf(0.5f * th), st = sinf(0.5f * th);
            float a = 0.5f * (phi + om), d = 0.5f * (phi - om);
            float ca = cosf(a), sa = sinf(a), cd = cosf(d), sd = sinf(d);
            float u00r =  ca * ct, u00i = -sa * ct;
            float u01r = -cd * st, u01i = -sd * st;
            float u10r =  cd * st, u10i = -sd * st;
            float u11r =  ca * ct, u11i =  sa * ct;
            const int bit = 1 << (3 - w);
            #pragma unroll
            for (int i = 0; i < 16; i++) {
                if (i & bit) continue;
                int j = i | bit;
                float ar = sr[i], ai = si[i], br = sr[j], bi = si[j];
                sr[i] = u00r * ar - u00i * ai + u01r * br - u01i * bi;
                si[i] = u00r * ai + u00i * ar + u01r * bi + u01i * br;
                sr[j] = u10r * ar - u10i * ai + u11r * br - u11i * bi;
                si[j] = u10r * ai + u10i * ar + u11r * bi + u11i * br;
            }
        }
        const int r = (l % 3) + 1;
        #pragma unroll
        for (int w = 0; w < 4; w++) {
            int tq = (w + r) & 3;
            const int cb = 1 << (3 - w), tb = 1 << (3 - tq);
            #pragma unroll
            for (int i = 0; i < 16; i++) {
                if ((i & cb) && !(i & tb)) {
                    int j = i | tb;
                    float tr = sr[i]; sr[i] = sr[j]; sr[j] = tr;
                    float ti = si[i]; si[i] = si[j]; si[j] = ti;
                }
            }
        }
    }

    #pragma unroll
    for (int w = 0; w < 4; w++) {
        const int bit = 1 << (3 - w);
        float e = 0.f;
        #pragma unroll
        for (int i = 0; i < 16; i++) {
            float p = sr[i] * sr[i] + si[i] * si[i];
            e += (i & bit) ? -p : p;
        }
        g_q[b * 4 + w] = e;
    }
}

// ============================================================================
// BACKEND: folded dconv1(scalar) + relu -> dconv2(f32x2) + sigmoid.
// 1 image per block, 8-channel groups, 3 CTAs/SM.
// ============================================================================
struct BackS {
    float sact[8][34][40];   // padded dconv1 group output (43.5KB)
    ull   dsw[432];          // dconv2 w dup: [(ic*3+dy)*3+o][dx]
    float sb[3];
};

__global__ __launch_bounds__(256, 3) void backend_kernel(
    const float* __restrict__ w2, const float* __restrict__ b2,
    float* __restrict__ out)
{
    extern __shared__ char raw[];
    BackS& S = *reinterpret_cast<BackS*>(raw);
    const int bidx = blockIdx.x, t = threadIdx.x;
    const int y = t >> 3, x0 = (t & 7) << 2;

    {
        float4 z = make_float4(0.f, 0.f, 0.f, 0.f);
        float4* p4 = reinterpret_cast<float4*>(&S.sact[0][0][0]);
        for (int i = t; i < 8 * 34 * 10; i += 256) p4[i] = z;
    }
    for (int i = t; i < 432; i += 256) {
        int dx = i % 3, j = i / 3;
        int o = j % 3, k = j / 3;
        int dy = k % 3, ic = k / 3;
        S.dsw[i] = dupbits(w2[((o * 16 + ic) * 3 + dy) * 3 + dx]);
    }
    if (t < 3) S.sb[t] = b2[t];

    float q0 = g_q[bidx * 4 + 0], q1 = g_q[bidx * 4 + 1];
    float q2 = g_q[bidx * 4 + 2], q3 = g_q[bidx * 4 + 3];
    __syncthreads();

    ull acc01[3], acc23[3];
    #pragma unroll
    for (int o = 0; o < 3; o++) {
        ull b = dupbits(S.sb[o]);
        acc01[o] = b; acc23[o] = b;
    }

    for (int g = 0; g < 2; g++) {
        // ---- stage 1: folded dconv1, oc group g (scalar, limited unroll) ----
        #pragma unroll 2
        for (int o8 = 0; o8 < 8; o8++) {
            int oc = g * 8 + o8;
            int idx = (oc << 10) + (y << 5) + x0;
            float4 a0 = g_A[idx], a1 = g_A[idx + 1], a2 = g_A[idx + 2], a3 = g_A[idx + 3];
            float4 be = *reinterpret_cast<const float4*>(&g_Beff[idx]);
            float v0 = fmaf(q0, a0.x, fmaf(q1, a0.y, fmaf(q2, a0.z, fmaf(q3, a0.w, be.x))));
            float v1 = fmaf(q0, a1.x, fmaf(q1, a1.y, fmaf(q2, a1.z, fmaf(q3, a1.w, be.y))));
            float v2 = fmaf(q0, a2.x, fmaf(q1, a2.y, fmaf(q2, a2.z, fmaf(q3, a2.w, be.z))));
            float v3 = fmaf(q0, a3.x, fmaf(q1, a3.y, fmaf(q2, a3.z, fmaf(q3, a3.w, be.w))));
            float4 r = make_float4(fmaxf(v0, 0.f), fmaxf(v1, 0.f),
                                   fmaxf(v2, 0.f), fmaxf(v3, 0.f));
            *reinterpret_cast<float4*>(&S.sact[o8][1 + y][4 + x0]) = r;
        }
        __syncthreads();

        // ---- stage 2: dconv2 partial over these 8 input channels (f32x2) ----
        #pragma unroll
        for (int icg = 0; icg < 8; icg++) {
            int ic16 = g * 8 + icg;
            #pragma unroll
            for (int dy = 0; dy < 3; dy++) {
                const float* base = &S.sact[icg][y + dy][0];
                float v0 = base[x0 + 3];
                float4 vm = *reinterpret_cast<const float4*>(base + x0 + 4);
                float v5 = base[x0 + 8];
                ull p0 = pk2(v0, vm.x), p1 = pk2(vm.x, vm.y), p2 = pk2(vm.y, vm.z);
                ull p3 = pk2(vm.z, vm.w), p4 = pk2(vm.w, v5);
                #pragma unroll
                for (int o = 0; o < 3; o++) {
                    int wi = ((ic16 * 3 + dy) * 3 + o) * 3;
                    ull w0 = S.dsw[wi], wA = S.dsw[wi + 1], wB = S.dsw[wi + 2];
                    acc01[o] = ffma2(p0, w0, acc01[o]);
                    acc01[o] = ffma2(p1, wA, acc01[o]);
                    acc01[o] = ffma2(p2, wB, acc01[o]);
                    acc23[o] = ffma2(p2, w0, acc23[o]);
                    acc23[o] = ffma2(p3, wA, acc23[o]);
                    acc23[o] = ffma2(p4, wB, acc23[o]);
                }
            }
        }
        __syncthreads();  // before next group overwrites sact
    }

    // ---- sigmoid epilogue ----
    float* ob = out + bidx * 3072;
    #pragma unroll
    for (int o = 0; o < 3; o++) {
        float2 l = upk2(acc01[o]), h = upk2(acc23[o]);
        float4 r = make_float4(1.f / (1.f + __expf(-l.x)),
                               1.f / (1.f + __expf(-l.y)),
                               1.f / (1.f + __expf(-h.x)),
                               1.f / (1.f + __expf(-h.y)));
        *reinterpret_cast<float4*>(&ob[(o << 10) + (y << 5) + x0]) = r;
    }
}

// ---------------- launch ----------------
extern "C" void kernel_launch(void* const* d_in, const int* in_sizes, int n_in,
                              void* d_out, int out_size)
{
    const float* x        = (const float*)d_in[0];
    const float* conv1_w  = (const float*)d_in[1];
    const float* conv1_b  = (const float*)d_in[2];
    const float* conv2_w  = (const float*)d_in[3];
    const float* conv2_b  = (const float*)d_in[4];
    const float* fc_w     = (const float*)d_in[5];
    const float* fc_b     = (const float*)d_in[6];
    const float* q_w      = (const float*)d_in[7];
    const float* fc2_w    = (const float*)d_in[8];
    const float* fc2_b    = (const float*)d_in[9];
    const float* dconv1_w = (const float*)d_in[10];
    const float* dconv1_b = (const float*)d_in[11];
    const float* dconv2_w = (const float*)d_in[12];
    const float* dconv2_b = (const float*)d_in[13];
    float* out = (float*)d_out;

    const int batch = in_sizes[0] / (3 * 32 * 32);

    cudaFuncSetAttribute(frontend_kernel, cudaFuncAttributeMaxDynamicSharedMemorySize,
                         (int)sizeof(FrontS));
    cudaFuncSetAttribute(backend_kernel, cudaFuncAttributeMaxDynamicSharedMemorySize,
                         (int)sizeof(BackS));

    prep_kernel<<<64, 256>>>(fc_w, fc2_w, fc2_b, dconv1_w, dconv1_b);
    frontend_kernel<<<batch, 256, sizeof(FrontS)>>>(x, conv1_w, conv1_b,
                                                    conv2_w, conv2_b, fc_b);
    quantum_kernel<<<(batch + 255) / 256, 256>>>(q_w, batch);
    backend_kernel<<<batch, 256, sizeof(BackS)>>>(dconv2_w, dconv2_b, out);
}

// round 4
// speedup vs baseline: 1.7519x; 1.1599x over previous
#include <cuda_runtime.h>
#include <math.h>

#define BATCH_MAX 2048

// ---------------- scratch (device globals; no allocation) ----------------
__device__ float4 g_fcwT[8192];          // fc_w transposed: [idx][k]
__device__ float4 g_A[16 * 1024];        // folded fc2+dconv1 weights: [oc*1024+px][k]
__device__ float  g_Beff[16 * 1024];     // folded bias
__device__ float  g_ang[BATCH_MAX * 4];  // angles out of frontend
__device__ float  g_q[BATCH_MAX * 4];    // quantum expvals
__device__ float  g_U[12 * 8];           // precomputed Rot gates: (l*4+w)*8 + {00r,00i,01r,01i,10r,10i,11r,11i}

// ---------------- prep: fc_w transpose + fc2/dconv1 fold + gate matrices ----------------
__global__ void prep_kernel(const float* __restrict__ fc_w,      // (4,8192)
                            const float* __restrict__ fc2_w,     // (8192,4)
                            const float* __restrict__ fc2_b,     // (8192)
                            const float* __restrict__ dconv1_w,  // (16,8,3,3)
                            const float* __restrict__ dconv1_b,  // (16)
                            const float* __restrict__ qw)        // (3,4,3)
{
    int i = blockIdx.x * blockDim.x + threadIdx.x;
    if (i < 12) {
        // Rot(phi, theta, omega) matrix for gate i = l*4+w
        float phi = qw[i * 3 + 0], th = qw[i * 3 + 1], om = qw[i * 3 + 2];
        float ct = cosf(0.5f * th), st = sinf(0.5f * th);
        float a = 0.5f * (phi + om), d = 0.5f * (phi - om);
        float ca = cosf(a), sa = sinf(a), cd = cosf(d), sd = sinf(d);
        float* u = &g_U[i * 8];
        u[0] =  ca * ct;  u[1] = -sa * ct;   // u00
        u[2] = -cd * st;  u[3] = -sd * st;   // u01
        u[4] =  cd * st;  u[5] = -sd * st;   // u10
        u[6] =  ca * ct;  u[7] =  sa * ct;   // u11
    }
    if (i < 8192) {
        g_fcwT[i] = make_float4(fc_w[i], fc_w[8192 + i], fc_w[16384 + i], fc_w[24576 + i]);
    }
    if (i < 16 * 1024) {
        int oc = i >> 10, px = i & 1023, y = px >> 5, x = px & 31;
        float s0 = 0.f, s1 = 0.f, s2 = 0.f, s3 = 0.f;
        float bs = dconv1_b[oc];
        for (int c = 0; c < 8; c++) {
            for (int dy = 0; dy < 3; dy++) {
                int iy = y + dy - 1;
                if ((unsigned)iy >= 32u) continue;
                for (int dx = 0; dx < 3; dx++) {
                    int ix = x + dx - 1;
                    if ((unsigned)ix >= 32u) continue;
                    int idx = (c << 10) + (iy << 5) + ix;
                    float w = dconv1_w[((oc * 8 + c) * 3 + dy) * 3 + dx];
                    float4 f = reinterpret_cast<const float4*>(fc2_w)[idx];
                    s0 = fmaf(w, f.x, s0);
                    s1 = fmaf(w, f.y, s1);
                    s2 = fmaf(w, f.z, s2);
                    s3 = fmaf(w, f.w, s3);
                    bs = fmaf(w, fc2_b[idx], bs);
                }
            }
        }
        g_A[i] = make_float4(s0, s1, s2, s3);
        g_Beff[i] = bs;
    }
}

// ============================================================================
// FRONTEND: conv1(4-oc groups)+relu -> conv2+relu -> fc.  All scalar FFMA.
// thread = (row y = t>>3, 4 contiguous px at x0 = (t&7)*4)
// ============================================================================
struct FrontS {
    float sx[3][34][40];     // padded input, data at [1+y][4+x]
    float sh1[4][34][40];    // padded conv1 group output (4 ch at a time)
    float sw1[432];          // conv1 w: [((ic*3+dy)*16+oc)*3+dx]
    float sw2[1152];         // conv2 w: [((ic*3+dy)*8+o)*3+dx]
    float sb1[16];
    float sb2[8];
    float red[8][4];
};

__global__ __launch_bounds__(256, 2) void frontend_kernel(
    const float* __restrict__ x,
    const float* __restrict__ w1, const float* __restrict__ b1,
    const float* __restrict__ w2, const float* __restrict__ b2,
    const float* __restrict__ fcb)
{
    extern __shared__ char raw[];
    FrontS& S = *reinterpret_cast<FrontS*>(raw);
    const int bidx = blockIdx.x, t = threadIdx.x;
    const int y = t >> 3, x0 = (t & 7) << 2;

    {
        float4 z = make_float4(0.f, 0.f, 0.f, 0.f);
        float4* px4 = reinterpret_cast<float4*>(&S.sx[0][0][0]);
        for (int i = t; i < 3 * 34 * 10; i += 256) px4[i] = z;
        float4* ph4 = reinterpret_cast<float4*>(&S.sh1[0][0][0]);
        for (int i = t; i < 4 * 34 * 10; i += 256) ph4[i] = z;
    }
    for (int i = t; i < 432; i += 256) {
        int dx = i % 3, j = i / 3;
        int oc = j % 16, k = j / 16;
        int dy = k % 3, ic = k / 3;
        S.sw1[i] = w1[((oc * 3 + ic) * 3 + dy) * 3 + dx];
    }
    for (int i = t; i < 1152; i += 256) {
        int dx = i % 3, j = i / 3;
        int o = j % 8, k = j / 8;
        int dy = k % 3, ic = k / 3;
        S.sw2[i] = w2[((o * 16 + ic) * 3 + dy) * 3 + dx];
    }
    if (t < 16) S.sb1[t] = b1[t];
    if (t < 8)  S.sb2[t] = b2[t];
    __syncthreads();

    const float* xb = x + bidx * 3072;
    for (int i = t; i < 3072; i += 256) {
        int c = i >> 10, p = i & 1023;
        S.sx[c][1 + (p >> 5)][4 + (p & 31)] = xb[i];
    }
    __syncthreads();

    // conv2 accumulators: 8 oc x 4 px (scalar)
    float acc2[8][4];
    #pragma unroll
    for (int o = 0; o < 8; o++) {
        float b = S.sb2[o];
        #pragma unroll
        for (int p = 0; p < 4; p++) acc2[o][p] = b;
    }

    for (int g = 0; g < 4; g++) {
        // ---- conv1, oc group g (4 oc) ----
        float a1[4][4];
        #pragma unroll
        for (int o = 0; o < 4; o++) {
            float b = S.sb1[g * 4 + o];
            #pragma unroll
            for (int p = 0; p < 4; p++) a1[o][p] = b;
        }
        #pragma unroll
        for (int ic = 0; ic < 3; ic++)
            #pragma unroll
            for (int dy = 0; dy < 3; dy++) {
                const float* base = &S.sx[ic][y + dy][0];
                float v0 = base[x0 + 3];
                float4 vm = *reinterpret_cast<const float4*>(base + x0 + 4);
                float v5 = base[x0 + 8];
                float v[6] = {v0, vm.x, vm.y, vm.z, vm.w, v5};
                #pragma unroll
                for (int o = 0; o < 4; o++) {
                    int wi = ((ic * 3 + dy) * 16 + g * 4 + o) * 3;
                    float w0 = S.sw1[wi], wA = S.sw1[wi + 1], wB = S.sw1[wi + 2];
                    #pragma unroll
                    for (int p = 0; p < 4; p++)
                        a1[o][p] = fmaf(v[p], w0, fmaf(v[p + 1], wA, fmaf(v[p + 2], wB, a1[o][p])));
                }
            }
        #pragma unroll
        for (int o = 0; o < 4; o++) {
            float4 r = make_float4(fmaxf(a1[o][0], 0.f), fmaxf(a1[o][1], 0.f),
                                   fmaxf(a1[o][2], 0.f), fmaxf(a1[o][3], 0.f));
            *reinterpret_cast<float4*>(&S.sh1[o][1 + y][4 + x0]) = r;
        }
        __syncthreads();

        // ---- conv2 partial over these 4 input channels ----
        #pragma unroll
        for (int icg = 0; icg < 4; icg++) {
            int ic16 = g * 4 + icg;
            #pragma unroll
            for (int dy = 0; dy < 3; dy++) {
                const float* base = &S.sh1[icg][y + dy][0];
                float v0 = base[x0 + 3];
                float4 vm = *reinterpret_cast<const float4*>(base + x0 + 4);
                float v5 = base[x0 + 8];
                float v[6] = {v0, vm.x, vm.y, vm.z, vm.w, v5};
                #pragma unroll
                for (int o = 0; o < 8; o++) {
                    int wi = ((ic16 * 3 + dy) * 8 + o) * 3;
                    float w0 = S.sw2[wi], wA = S.sw2[wi + 1], wB = S.sw2[wi + 2];
                    #pragma unroll
                    for (int p = 0; p < 4; p++)
                        acc2[o][p] = fmaf(v[p], w0, fmaf(v[p + 1], wA, fmaf(v[p + 2], wB, acc2[o][p])));
                }
            }
        }
        __syncthreads();  // before next group overwrites sh1
    }

    // ---- relu + fc into 4 angle partials ----
    float angk[4] = {0.f, 0.f, 0.f, 0.f};
    #pragma unroll
    for (int o = 0; o < 8; o++) {
        #pragma unroll
        for (int p = 0; p < 4; p++) {
            float v = fmaxf(acc2[o][p], 0.f);
            float4 f = g_fcwT[(o << 10) + (y << 5) + x0 + p];
            angk[0] = fmaf(v, f.x, angk[0]);
            angk[1] = fmaf(v, f.y, angk[1]);
            angk[2] = fmaf(v, f.z, angk[2]);
            angk[3] = fmaf(v, f.w, angk[3]);
        }
    }
    #pragma unroll
    for (int k = 0; k < 4; k++)
        #pragma unroll
        for (int off = 16; off > 0; off >>= 1)
            angk[k] += __shfl_xor_sync(0xffffffffu, angk[k], off);
    const int wrp = t >> 5, ln = t & 31;
    if (ln == 0) {
        #pragma unroll
        for (int k = 0; k < 4; k++) S.red[wrp][k] = angk[k];
    }
    __syncthreads();
    if (t < 4) {
        float s = 0.f;
        #pragma unroll
        for (int w = 0; w < 8; w++) s += S.red[w][t];
        g_ang[bidx * 4 + t] = s + fcb[t];
    }
}

// ---------------- quantum: 1 thread = 1 batch element (gates precomputed) ----------------
__global__ void quantum_kernel(int batch)
{
    int b = blockIdx.x * blockDim.x + threadIdx.x;
    if (b >= batch) return;

    float sr[16], si[16];
    #pragma unroll
    for (int i = 0; i < 16; i++) { sr[i] = 0.f; si[i] = 0.f; }
    sr[0] = 1.f;

    #pragma unroll
    for (int w = 0; w < 4; w++) {
        float h = 0.5f * g_ang[b * 4 + w];
        float c = cosf(h), s = sinf(h);
        const int bit = 1 << (3 - w);
        #pragma unroll
        for (int i = 0; i < 16; i++) {
            if (i & bit) continue;
            int j = i | bit;
            float ar = sr[i], ai = si[i], br = sr[j], bi = si[j];
            sr[i] = fmaf(c, ar,  s * bi);  si[i] = fmaf(c, ai, -s * br);
            sr[j] = fmaf(c, br,  s * ai);  si[j] = fmaf(c, bi, -s * ar);
        }
    }

    #pragma unroll
    for (int l = 0; l < 3; l++) {
        #pragma unroll
        for (int w = 0; w < 4; w++) {
            const float* u = &g_U[(l * 4 + w) * 8];
            float u00r = u[0], u00i = u[1], u01r = u[2], u01i = u[3];
            float u10r = u[4], u10i = u[5], u11r = u[6], u11i = u[7];
            const int bit = 1 << (3 - w);
            #pragma unroll
            for (int i = 0; i < 16; i++) {
                if (i & bit) continue;
                int j = i | bit;
                float ar = sr[i], ai = si[i], br = sr[j], bi = si[j];
                sr[i] = u00r * ar - u00i * ai + u01r * br - u01i * bi;
                si[i] = u00r * ai + u00i * ar + u01r * bi + u01i * br;
                sr[j] = u10r * ar - u10i * ai + u11r * br - u11i * bi;
                si[j] = u10r * ai + u10i * ar + u11r * bi + u11i * br;
            }
        }
        const int r = (l % 3) + 1;
        #pragma unroll
        for (int w = 0; w < 4; w++) {
            int tq = (w + r) & 3;
            const int cb = 1 << (3 - w), tb = 1 << (3 - tq);
            #pragma unroll
            for (int i = 0; i < 16; i++) {
                if ((i & cb) && !(i & tb)) {
                    int j = i | tb;
                    float tr = sr[i]; sr[i] = sr[j]; sr[j] = tr;
                    float ti = si[i]; si[i] = si[j]; si[j] = ti;
                }
            }
        }
    }

    #pragma unroll
    for (int w = 0; w < 4; w++) {
        const int bit = 1 << (3 - w);
        float e = 0.f;
        #pragma unroll
        for (int i = 0; i < 16; i++) {
            float p = sr[i] * sr[i] + si[i] * si[i];
            e += (i & bit) ? -p : p;
        }
        g_q[b * 4 + w] = e;
    }
}

// ============================================================================
// BACKEND: folded dconv1 + relu -> dconv2 + sigmoid.  All scalar FFMA.
// 1 image per block, 8-channel groups.
// ============================================================================
struct BackS {
    float sact[8][34][40];   // padded dconv1 group output (43.5KB)
    float sw[432];           // dconv2 w: [((ic*3+dy)*3+o)*3+dx]
    float sb[3];
};

__global__ __launch_bounds__(256, 3) void backend_kernel(
    const float* __restrict__ w2, const float* __restrict__ b2,
    float* __restrict__ out)
{
    extern __shared__ char raw[];
    BackS& S = *reinterpret_cast<BackS*>(raw);
    const int bidx = blockIdx.x, t = threadIdx.x;
    const int y = t >> 3, x0 = (t & 7) << 2;

    {
        float4 z = make_float4(0.f, 0.f, 0.f, 0.f);
        float4* p4 = reinterpret_cast<float4*>(&S.sact[0][0][0]);
        for (int i = t; i < 8 * 34 * 10; i += 256) p4[i] = z;
    }
    for (int i = t; i < 432; i += 256) {
        int dx = i % 3, j = i / 3;
        int o = j % 3, k = j / 3;
        int dy = k % 3, ic = k / 3;
        S.sw[i] = w2[((o * 16 + ic) * 3 + dy) * 3 + dx];
    }
    if (t < 3) S.sb[t] = b2[t];

    float q0 = g_q[bidx * 4 + 0], q1 = g_q[bidx * 4 + 1];
    float q2 = g_q[bidx * 4 + 2], q3 = g_q[bidx * 4 + 3];
    __syncthreads();

    float acc[3][4];
    #pragma unroll
    for (int o = 0; o < 3; o++) {
        float b = S.sb[o];
        #pragma unroll
        for (int p = 0; p < 4; p++) acc[o][p] = b;
    }

    for (int g = 0; g < 2; g++) {
        // ---- stage 1: folded dconv1, oc group g (limited unroll vs reg pressure) ----
        #pragma unroll 2
        for (int o8 = 0; o8 < 8; o8++) {
            int oc = g * 8 + o8;
            int idx = (oc << 10) + (y << 5) + x0;
            float4 a0 = g_A[idx], a1 = g_A[idx + 1], a2 = g_A[idx + 2], a3 = g_A[idx + 3];
            float4 be = *reinterpret_cast<const float4*>(&g_Beff[idx]);
            float v0 = fmaf(q0, a0.x, fmaf(q1, a0.y, fmaf(q2, a0.z, fmaf(q3, a0.w, be.x))));
            float v1 = fmaf(q0, a1.x, fmaf(q1, a1.y, fmaf(q2, a1.z, fmaf(q3, a1.w, be.y))));
            float v2 = fmaf(q0, a2.x, fmaf(q1, a2.y, fmaf(q2, a2.z, fmaf(q3, a2.w, be.z))));
            float v3 = fmaf(q0, a3.x, fmaf(q1, a3.y, fmaf(q2, a3.z, fmaf(q3, a3.w, be.w))));
            float4 r = make_float4(fmaxf(v0, 0.f), fmaxf(v1, 0.f),
                                   fmaxf(v2, 0.f), fmaxf(v3, 0.f));
            *reinterpret_cast<float4*>(&S.sact[o8][1 + y][4 + x0]) = r;
        }
        __syncthreads();

        // ---- stage 2: dconv2 partial over these 8 input channels (scalar) ----
        #pragma unroll
        for (int icg = 0; icg < 8; icg++) {
            int ic16 = g * 8 + icg;
            #pragma unroll
            for (int dy = 0; dy < 3; dy++) {
                const float* base = &S.sact[icg][y + dy][0];
                float v0 = base[x0 + 3];
                float4 vm = *reinterpret_cast<const float4*>(base + x0 + 4);
                float v5 = base[x0 + 8];
                float v[6] = {v0, vm.x, vm.y, vm.z, vm.w, v5};
                #pragma unroll
                for (int o = 0; o < 3; o++) {
                    int wi = ((ic16 * 3 + dy) * 3 + o) * 3;
                    float w0 = S.sw[wi], wA = S.sw[wi + 1], wB = S.sw[wi + 2];
                    #pragma unroll
                    for (int p = 0; p < 4; p++)
                        acc[o][p] = fmaf(v[p], w0, fmaf(v[p + 1], wA, fmaf(v[p + 2], wB, acc[o][p])));
                }
            }
        }
        __syncthreads();  // before next group overwrites sact
    }

    // ---- sigmoid epilogue ----
    float* ob = out + bidx * 3072;
    #pragma unroll
    for (int o = 0; o < 3; o++) {
        float4 r = make_float4(1.f / (1.f + __expf(-acc[o][0])),
                               1.f / (1.f + __expf(-acc[o][1])),
                               1.f / (1.f + __expf(-acc[o][2])),
                               1.f / (1.f + __expf(-acc[o][3])));
        *reinterpret_cast<float4*>(&ob[(o << 10) + (y << 5) + x0]) = r;
    }
}

// ---------------- launch ----------------
extern "C" void kernel_launch(void* const* d_in, const int* in_sizes, int n_in,
                              void* d_out, int out_size)
{
    const float* x        = (const float*)d_in[0];
    const float* conv1_w  = (const float*)d_in[1];
    const float* conv1_b  = (const float*)d_in[2];
    const float* conv2_w  = (const float*)d_in[3];
    const float* conv2_b  = (const float*)d_in[4];
    const float* fc_w     = (const float*)d_in[5];
    const float* fc_b     = (const float*)d_in[6];
    const float* q_w      = (const float*)d_in[7];
    const float* fc2_w    = (const float*)d_in[8];
    const float* fc2_b    = (const float*)d_in[9];
    const float* dconv1_w = (const float*)d_in[10];
    const float* dconv1_b = (const float*)d_in[11];
    const float* dconv2_w = (const float*)d_in[12];
    const float* dconv2_b = (const float*)d_in[13];
    float* out = (float*)d_out;

    const int batch = in_sizes[0] / (3 * 32 * 32);

    cudaFuncSetAttribute(frontend_kernel, cudaFuncAttributeMaxDynamicSharedMemorySize,
                         (int)sizeof(FrontS));
    cudaFuncSetAttribute(backend_kernel, cudaFuncAttributeMaxDynamicSharedMemorySize,
                         (int)sizeof(BackS));

    prep_kernel<<<64, 256>>>(fc_w, fc2_w, fc2_b, dconv1_w, dconv1_b, q_w);
    frontend_kernel<<<batch, 256, sizeof(FrontS)>>>(x, conv1_w, conv1_b,
                                                    conv2_w, conv2_b, fc_b);
    quantum_kernel<<<(batch + 255) / 256, 256>>>(batch);
    backend_kernel<<<batch, 256, sizeof(BackS)>>>(dconv2_w, dconv2_b, out);
}

// round 5
// speedup vs baseline: 2.0192x; 1.1526x over previous
#include <cuda_runtime.h>
#include <math.h>

#define BATCH_MAX 2048

// ---------------- scratch (device globals; no allocation) ----------------
__device__ float4 g_fcwT[8192];          // fc_w transposed: [idx][k]
__device__ float4 g_A[16 * 1024];        // folded fc2+dconv1 weights: [oc*1024+px][k]
__device__ float  g_Beff[16 * 1024];     // folded bias
__device__ float  g_ang[BATCH_MAX * 4];  // angles out of frontend
__device__ float  g_q[BATCH_MAX * 4];    // quantum expvals
__device__ float  g_U[12 * 8];           // precomputed Rot gates

// ---------------- prep ----------------
__global__ void prep_kernel(const float* __restrict__ fc_w,
                            const float* __restrict__ fc2_w,
                            const float* __restrict__ fc2_b,
                            const float* __restrict__ dconv1_w,
                            const float* __restrict__ dconv1_b,
                            const float* __restrict__ qw)
{
    int i = blockIdx.x * blockDim.x + threadIdx.x;
    if (i < 12) {
        float phi = qw[i * 3 + 0], th = qw[i * 3 + 1], om = qw[i * 3 + 2];
        float ct = cosf(0.5f * th), st = sinf(0.5f * th);
        float a = 0.5f * (phi + om), d = 0.5f * (phi - om);
        float ca = cosf(a), sa = sinf(a), cd = cosf(d), sd = sinf(d);
        float* u = &g_U[i * 8];
        u[0] =  ca * ct;  u[1] = -sa * ct;
        u[2] = -cd * st;  u[3] = -sd * st;
        u[4] =  cd * st;  u[5] = -sd * st;
        u[6] =  ca * ct;  u[7] =  sa * ct;
    }
    if (i < 8192) {
        g_fcwT[i] = make_float4(fc_w[i], fc_w[8192 + i], fc_w[16384 + i], fc_w[24576 + i]);
    }
    if (i < 16 * 1024) {
        int oc = i >> 10, px = i & 1023, y = px >> 5, x = px & 31;
        float s0 = 0.f, s1 = 0.f, s2 = 0.f, s3 = 0.f;
        float bs = dconv1_b[oc];
        for (int c = 0; c < 8; c++) {
            for (int dy = 0; dy < 3; dy++) {
                int iy = y + dy - 1;
                if ((unsigned)iy >= 32u) continue;
                for (int dx = 0; dx < 3; dx++) {
                    int ix = x + dx - 1;
                    if ((unsigned)ix >= 32u) continue;
                    int idx = (c << 10) + (iy << 5) + ix;
                    float w = dconv1_w[((oc * 8 + c) * 3 + dy) * 3 + dx];
                    float4 f = reinterpret_cast<const float4*>(fc2_w)[idx];
                    s0 = fmaf(w, f.x, s0);
                    s1 = fmaf(w, f.y, s1);
                    s2 = fmaf(w, f.z, s2);
                    s3 = fmaf(w, f.w, s3);
                    bs = fmaf(w, fc2_b[idx], bs);
                }
            }
        }
        g_A[i] = make_float4(s0, s1, s2, s3);
        g_Beff[i] = bs;
    }
}

// halo helper: v0/v5 from neighbor lanes via shuffle (pad=0 at tile edge)
__device__ __forceinline__ void halo6(const float* base, int x0, int lane7,
                                      float v[6])
{
    float4 vm = *reinterpret_cast<const float4*>(base + 4 + x0);
    float v0 = __shfl_up_sync(0xffffffffu, vm.w, 1);
    float v5 = __shfl_down_sync(0xffffffffu, vm.x, 1);
    if (lane7 == 0) v0 = 0.f;
    if (lane7 == 7) v5 = 0.f;
    v[0] = v0; v[1] = vm.x; v[2] = vm.y; v[3] = vm.z; v[4] = vm.w; v[5] = v5;
}

// ============================================================================
// FRONTEND: conv1(4-oc groups)+relu -> conv2+relu -> fc.  Scalar FFMA.
// thread = (row y = t>>3, 4 contiguous px at x0 = (t&7)*4)
// ============================================================================
struct FrontS {
    float sx[3][34][40];
    float sh1[4][34][40];
    float sw1[432];
    float sw2[1152];
    float sb1[16];
    float sb2[8];
    float red[8][4];
};

__global__ __launch_bounds__(256, 3) void frontend_kernel(
    const float* __restrict__ x,
    const float* __restrict__ w1, const float* __restrict__ b1,
    const float* __restrict__ w2, const float* __restrict__ b2,
    const float* __restrict__ fcb)
{
    extern __shared__ char raw[];
    FrontS& S = *reinterpret_cast<FrontS*>(raw);
    const int bidx = blockIdx.x, t = threadIdx.x;
    const int y = t >> 3, x0 = (t & 7) << 2;
    const int lane7 = t & 7;

    {
        float4 z = make_float4(0.f, 0.f, 0.f, 0.f);
        float4* px4 = reinterpret_cast<float4*>(&S.sx[0][0][0]);
        for (int i = t; i < 3 * 34 * 10; i += 256) px4[i] = z;
        float4* ph4 = reinterpret_cast<float4*>(&S.sh1[0][0][0]);
        for (int i = t; i < 4 * 34 * 10; i += 256) ph4[i] = z;
    }
    for (int i = t; i < 432; i += 256) {
        int dx = i % 3, j = i / 3;
        int oc = j % 16, k = j / 16;
        int dy = k % 3, ic = k / 3;
        S.sw1[i] = w1[((oc * 3 + ic) * 3 + dy) * 3 + dx];
    }
    for (int i = t; i < 1152; i += 256) {
        int dx = i % 3, j = i / 3;
        int o = j % 8, k = j / 8;
        int dy = k % 3, ic = k / 3;
        S.sw2[i] = w2[((o * 16 + ic) * 3 + dy) * 3 + dx];
    }
    if (t < 16) S.sb1[t] = b1[t];
    if (t < 8)  S.sb2[t] = b2[t];
    __syncthreads();

    const float* xb = x + bidx * 3072;
    for (int i = t; i < 3072; i += 256) {
        int c = i >> 10, p = i & 1023;
        S.sx[c][1 + (p >> 5)][4 + (p & 31)] = xb[i];
    }
    __syncthreads();

    float acc2[8][4];
    #pragma unroll
    for (int o = 0; o < 8; o++) {
        float b = S.sb2[o];
        #pragma unroll
        for (int p = 0; p < 4; p++) acc2[o][p] = b;
    }

    for (int g = 0; g < 4; g++) {
        // ---- conv1, oc group g (4 oc) ----
        float a1[4][4];
        #pragma unroll
        for (int o = 0; o < 4; o++) {
            float b = S.sb1[g * 4 + o];
            #pragma unroll
            for (int p = 0; p < 4; p++) a1[o][p] = b;
        }
        #pragma unroll
        for (int ic = 0; ic < 3; ic++)
            #pragma unroll
            for (int dy = 0; dy < 3; dy++) {
                float v[6];
                halo6(&S.sx[ic][y + dy][0], x0, lane7, v);
                #pragma unroll
                for (int o = 0; o < 4; o++) {
                    int wi = ((ic * 3 + dy) * 16 + g * 4 + o) * 3;
                    float w0 = S.sw1[wi], wA = S.sw1[wi + 1], wB = S.sw1[wi + 2];
                    #pragma unroll
                    for (int p = 0; p < 4; p++)
                        a1[o][p] = fmaf(v[p], w0, fmaf(v[p + 1], wA, fmaf(v[p + 2], wB, a1[o][p])));
                }
            }
        #pragma unroll
        for (int o = 0; o < 4; o++) {
            float4 r = make_float4(fmaxf(a1[o][0], 0.f), fmaxf(a1[o][1], 0.f),
                                   fmaxf(a1[o][2], 0.f), fmaxf(a1[o][3], 0.f));
            *reinterpret_cast<float4*>(&S.sh1[o][1 + y][4 + x0]) = r;
        }
        __syncthreads();

        // ---- conv2 partial over these 4 input channels ----
        #pragma unroll
        for (int icg = 0; icg < 4; icg++) {
            int ic16 = g * 4 + icg;
            #pragma unroll
            for (int dy = 0; dy < 3; dy++) {
                float v[6];
                halo6(&S.sh1[icg][y + dy][0], x0, lane7, v);
                #pragma unroll
                for (int o = 0; o < 8; o++) {
                    int wi = ((ic16 * 3 + dy) * 8 + o) * 3;
                    float w0 = S.sw2[wi], wA = S.sw2[wi + 1], wB = S.sw2[wi + 2];
                    #pragma unroll
                    for (int p = 0; p < 4; p++)
                        acc2[o][p] = fmaf(v[p], w0, fmaf(v[p + 1], wA, fmaf(v[p + 2], wB, acc2[o][p])));
                }
            }
        }
        __syncthreads();
    }

    // ---- relu + fc ----
    float angk[4] = {0.f, 0.f, 0.f, 0.f};
    #pragma unroll
    for (int o = 0; o < 8; o++) {
        #pragma unroll
        for (int p = 0; p < 4; p++) {
            float v = fmaxf(acc2[o][p], 0.f);
            float4 f = g_fcwT[(o << 10) + (y << 5) + x0 + p];
            angk[0] = fmaf(v, f.x, angk[0]);
            angk[1] = fmaf(v, f.y, angk[1]);
            angk[2] = fmaf(v, f.z, angk[2]);
            angk[3] = fmaf(v, f.w, angk[3]);
        }
    }
    #pragma unroll
    for (int k = 0; k < 4; k++)
        #pragma unroll
        for (int off = 16; off > 0; off >>= 1)
            angk[k] += __shfl_xor_sync(0xffffffffu, angk[k], off);
    const int wrp = t >> 5, ln = t & 31;
    if (ln == 0) {
        #pragma unroll
        for (int k = 0; k < 4; k++) S.red[wrp][k] = angk[k];
    }
    __syncthreads();
    if (t < 4) {
        float s = 0.f;
        #pragma unroll
        for (int w = 0; w < 8; w++) s += S.red[w][t];
        g_ang[bidx * 4 + t] = s + fcb[t];
    }
}

// ---------------- quantum ----------------
__global__ void quantum_kernel(int batch)
{
    int b = blockIdx.x * blockDim.x + threadIdx.x;
    if (b >= batch) return;

    float sr[16], si[16];
    #pragma unroll
    for (int i = 0; i < 16; i++) { sr[i] = 0.f; si[i] = 0.f; }
    sr[0] = 1.f;

    #pragma unroll
    for (int w = 0; w < 4; w++) {
        float h = 0.5f * g_ang[b * 4 + w];
        float c = cosf(h), s = sinf(h);
        const int bit = 1 << (3 - w);
        #pragma unroll
        for (int i = 0; i < 16; i++) {
            if (i & bit) continue;
            int j = i | bit;
            float ar = sr[i], ai = si[i], br = sr[j], bi = si[j];
            sr[i] = fmaf(c, ar,  s * bi);  si[i] = fmaf(c, ai, -s * br);
            sr[j] = fmaf(c, br,  s * ai);  si[j] = fmaf(c, bi, -s * ar);
        }
    }

    #pragma unroll
    for (int l = 0; l < 3; l++) {
        #pragma unroll
        for (int w = 0; w < 4; w++) {
            const float* u = &g_U[(l * 4 + w) * 8];
            float u00r = u[0], u00i = u[1], u01r = u[2], u01i = u[3];
            float u10r = u[4], u10i = u[5], u11r = u[6], u11i = u[7];
            const int bit = 1 << (3 - w);
            #pragma unroll
            for (int i = 0; i < 16; i++) {
                if (i & bit) continue;
                int j = i | bit;
                float ar = sr[i], ai = si[i], br = sr[j], bi = si[j];
                sr[i] = u00r * ar - u00i * ai + u01r * br - u01i * bi;
                si[i] = u00r * ai + u00i * ar + u01r * bi + u01i * br;
                sr[j] = u10r * ar - u10i * ai + u11r * br - u11i * bi;
                si[j] = u10r * ai + u10i * ar + u11r * bi + u11i * br;
            }
        }
        const int r = (l % 3) + 1;
        #pragma unroll
        for (int w = 0; w < 4; w++) {
            int tq = (w + r) & 3;
            const int cb = 1 << (3 - w), tb = 1 << (3 - tq);
            #pragma unroll
            for (int i = 0; i < 16; i++) {
                if ((i & cb) && !(i & tb)) {
                    int j = i | tb;
                    float tr = sr[i]; sr[i] = sr[j]; sr[j] = tr;
                    float ti = si[i]; si[i] = si[j]; si[j] = ti;
                }
            }
        }
    }

    #pragma unroll
    for (int w = 0; w < 4; w++) {
        const int bit = 1 << (3 - w);
        float e = 0.f;
        #pragma unroll
        for (int i = 0; i < 16; i++) {
            float p = sr[i] * sr[i] + si[i] * si[i];
            e += (i & bit) ? -p : p;
        }
        g_q[b * 4 + w] = e;
    }
}

// ============================================================================
// BACKEND: folded dconv1 + relu -> dconv2 + sigmoid.  2 images/block.
// ============================================================================
struct BackS {
    float sact[2][8][34][40];  // 87,040 B
    float sw[432];
    float sb[3];
};

__global__ __launch_bounds__(256, 2) void backend_kernel(
    const float* __restrict__ w2, const float* __restrict__ b2,
    float* __restrict__ out)
{
    extern __shared__ char raw[];
    BackS& S = *reinterpret_cast<BackS*>(raw);
    const int bid = blockIdx.x, t = threadIdx.x;
    const int b0 = 2 * bid;
    const int y = t >> 3, x0 = (t & 7) << 2;
    const int lane7 = t & 7;

    {
        float4 z = make_float4(0.f, 0.f, 0.f, 0.f);
        float4* p4 = reinterpret_cast<float4*>(&S.sact[0][0][0][0]);
        for (int i = t; i < 2 * 8 * 34 * 10; i += 256) p4[i] = z;
    }
    for (int i = t; i < 432; i += 256) {
        int dx = i % 3, j = i / 3;
        int o = j % 3, k = j / 3;
        int dy = k % 3, ic = k / 3;
        S.sw[i] = w2[((o * 16 + ic) * 3 + dy) * 3 + dx];
    }
    if (t < 3) S.sb[t] = b2[t];

    float qa[4], qb[4];
    #pragma unroll
    for (int k = 0; k < 4; k++) {
        qa[k] = g_q[b0 * 4 + k];
        qb[k] = g_q[(b0 + 1) * 4 + k];
    }
    __syncthreads();

    float acc[2][3][4];
    #pragma unroll
    for (int o = 0; o < 3; o++) {
        float b = S.sb[o];
        #pragma unroll
        for (int p = 0; p < 4; p++) { acc[0][o][p] = b; acc[1][o][p] = b; }
    }

    for (int g = 0; g < 2; g++) {
        // ---- stage 1: folded dconv1, oc group g, both images ----
        #pragma unroll 2
        for (int o8 = 0; o8 < 8; o8++) {
            int oc = g * 8 + o8;
            int idx = (oc << 10) + (y << 5) + x0;
            float4 a0 = g_A[idx], a1 = g_A[idx + 1], a2 = g_A[idx + 2], a3 = g_A[idx + 3];
            float4 be = *reinterpret_cast<const float4*>(&g_Beff[idx]);
            {
                float v0 = fmaf(qa[0], a0.x, fmaf(qa[1], a0.y, fmaf(qa[2], a0.z, fmaf(qa[3], a0.w, be.x))));
                float v1 = fmaf(qa[0], a1.x, fmaf(qa[1], a1.y, fmaf(qa[2], a1.z, fmaf(qa[3], a1.w, be.y))));
                float v2 = fmaf(qa[0], a2.x, fmaf(qa[1], a2.y, fmaf(qa[2], a2.z, fmaf(qa[3], a2.w, be.z))));
                float v3 = fmaf(qa[0], a3.x, fmaf(qa[1], a3.y, fmaf(qa[2], a3.z, fmaf(qa[3], a3.w, be.w))));
                *reinterpret_cast<float4*>(&S.sact[0][o8][1 + y][4 + x0]) =
                    make_float4(fmaxf(v0, 0.f), fmaxf(v1, 0.f), fmaxf(v2, 0.f), fmaxf(v3, 0.f));
            }
            {
                float v0 = fmaf(qb[0], a0.x, fmaf(qb[1], a0.y, fmaf(qb[2], a0.z, fmaf(qb[3], a0.w, be.x))));
                float v1 = fmaf(qb[0], a1.x, fmaf(qb[1], a1.y, fmaf(qb[2], a1.z, fmaf(qb[3], a1.w, be.y))));
                float v2 = fmaf(qb[0], a2.x, fmaf(qb[1], a2.y, fmaf(qb[2], a2.z, fmaf(qb[3], a2.w, be.z))));
                float v3 = fmaf(qb[0], a3.x, fmaf(qb[1], a3.y, fmaf(qb[2], a3.z, fmaf(qb[3], a3.w, be.w))));
                *reinterpret_cast<float4*>(&S.sact[1][o8][1 + y][4 + x0]) =
                    make_float4(fmaxf(v0, 0.f), fmaxf(v1, 0.f), fmaxf(v2, 0.f), fmaxf(v3, 0.f));
            }
        }
        __syncthreads();

        // ---- stage 2: dconv2 partial, both images ----
        #pragma unroll
        for (int img = 0; img < 2; img++) {
            #pragma unroll
            for (int icg = 0; icg < 8; icg++) {
                int ic16 = g * 8 + icg;
                #pragma unroll
                for (int dy = 0; dy < 3; dy++) {
                    float v[6];
                    halo6(&S.sact[img][icg][y + dy][0], x0, lane7, v);
                    #pragma unroll
                    for (int o = 0; o < 3; o++) {
                        int wi = ((ic16 * 3 + dy) * 3 + o) * 3;
                        float w0 = S.sw[wi], wA = S.sw[wi + 1], wB = S.sw[wi + 2];
                        #pragma unroll
                        for (int p = 0; p < 4; p++)
                            acc[img][o][p] = fmaf(v[p], w0,
                                fmaf(v[p + 1], wA, fmaf(v[p + 2], wB, acc[img][o][p])));
                    }
                }
            }
        }
        __syncthreads();
    }

    // ---- sigmoid epilogue, both images ----
    #pragma unroll
    for (int img = 0; img < 2; img++) {
        float* ob = out + (b0 + img) * 3072;
        #pragma unroll
        for (int o = 0; o < 3; o++) {
            float4 r = make_float4(1.f / (1.f + __expf(-acc[img][o][0])),
                                   1.f / (1.f + __expf(-acc[img][o][1])),
                                   1.f / (1.f + __expf(-acc[img][o][2])),
                                   1.f / (1.f + __expf(-acc[img][o][3])));
            *reinterpret_cast<float4*>(&ob[(o << 10) + (y << 5) + x0]) = r;
        }
    }
}

// ---------------- launch ----------------
extern "C" void kernel_launch(void* const* d_in, const int* in_sizes, int n_in,
                              void* d_out, int out_size)
{
    const float* x        = (const float*)d_in[0];
    const float* conv1_w  = (const float*)d_in[1];
    const float* conv1_b  = (const float*)d_in[2];
    const float* conv2_w  = (const float*)d_in[3];
    const float* conv2_b  = (const float*)d_in[4];
    const float* fc_w     = (const float*)d_in[5];
    const float* fc_b     = (const float*)d_in[6];
    const float* q_w      = (const float*)d_in[7];
    const float* fc2_w    = (const float*)d_in[8];
    const float* fc2_b    = (const float*)d_in[9];
    const float* dconv1_w = (const float*)d_in[10];
    const float* dconv1_b = (const float*)d_in[11];
    const float* dconv2_w = (const float*)d_in[12];
    const float* dconv2_b = (const float*)d_in[13];
    float* out = (float*)d_out;

    const int batch = in_sizes[0] / (3 * 32 * 32);

    cudaFuncSetAttribute(frontend_kernel, cudaFuncAttributeMaxDynamicSharedMemorySize,
                         (int)sizeof(FrontS));
    cudaFuncSetAttribute(backend_kernel, cudaFuncAttributeMaxDynamicSharedMemorySize,
                         (int)sizeof(BackS));

    prep_kernel<<<64, 256>>>(fc_w, fc2_w, fc2_b, dconv1_w, dconv1_b, q_w);
    frontend_kernel<<<batch, 256, sizeof(FrontS)>>>(x, conv1_w, conv1_b,
                                                    conv2_w, conv2_b, fc_b);
    quantum_kernel<<<(batch + 255) / 256, 256>>>(batch);
    backend_kernel<<<batch / 2, 256, sizeof(BackS)>>>(dconv2_w, dconv2_b, out);
}